// round 7
// baseline (speedup 1.0000x reference)
#include <cuda_runtime.h>
#include <math.h>
#include <stdint.h>

// Problem dims
constexpr int BB = 8;
constexpr int SS = 1024;
constexpr int DD = 256;
constexpr int MTOT = BB * SS;          // 8192
constexpr int PAD = 32 * DD;

// Scratch (device globals — no cudaMalloc allowed)
__device__ float g_q[MTOT * DD + PAD];
__device__ float g_k[MTOT * DD + PAD];
__device__ float g_f[MTOT * DD + PAD];
__device__ float g_i[MTOT * DD + PAD];
__device__ float g_n[MTOT * DD];
__device__ float g_h[MTOT * DD];
__device__ float g_inv[MTOT + 64];

typedef unsigned long long ull;

// ---- f32x2 helpers ----
__device__ __forceinline__ ull pack2(float lo, float hi) {
    ull r; asm("mov.b64 %0, {%1, %2};" : "=l"(r) : "f"(lo), "f"(hi)); return r;
}
__device__ __forceinline__ ull fma2(ull a, ull b, ull c) {
    ull d; asm("fma.rn.f32x2 %0, %1, %2, %3;" : "=l"(d) : "l"(a), "l"(b), "l"(c)); return d;
}
__device__ __forceinline__ ull mul2(ull a, ull b) {
    ull d; asm("mul.rn.f32x2 %0, %1, %2;" : "=l"(d) : "l"(a), "l"(b)); return d;
}
__device__ __forceinline__ ull add2(ull a, ull b) {
    ull d; asm("add.rn.f32x2 %0, %1, %2;" : "=l"(d) : "l"(a), "l"(b)); return d;
}
__device__ __forceinline__ void unpack2(ull v, float& lo, float& hi) {
    asm("mov.b64 {%0, %1}, %2;" : "=f"(lo), "=f"(hi) : "l"(v));
}
__device__ __forceinline__ float hsum2(ull v) {
    float lo, hi; unpack2(v, lo, hi); return lo + hi;
}

// ---- cp.async helpers ----
__device__ __forceinline__ void cp_async16(uint32_t saddr, const void* gptr) {
    asm volatile("cp.async.ca.shared.global [%0], [%1], 16;" :: "r"(saddr), "l"(gptr));
}
__device__ __forceinline__ void cp_async4(uint32_t saddr, const void* gptr) {
    asm volatile("cp.async.ca.shared.global [%0], [%1], 4;" :: "r"(saddr), "l"(gptr));
}
__device__ __forceinline__ void cp_commit() { asm volatile("cp.async.commit_group;"); }
template <int N>
__device__ __forceinline__ void cp_wait() {
    asm volatile("cp.async.wait_group %0;" :: "n"(N));
}

// ---------------------------------------------------------------------------
// GEMM (unchanged): 128x128 tile, BK=8, 256 thr, 8x8/thread, f32x2.
// ---------------------------------------------------------------------------
template <int ACT>
__global__ void __launch_bounds__(256) gemm_kernel(
    const float* __restrict__ A, const float* __restrict__ W,
    const float* __restrict__ bias, float* __restrict__ out)
{
    __shared__ float As[8][132];
    __shared__ float Bs[8][132];

    const int tid = threadIdx.x;
    const int m0 = blockIdx.y * 128;
    const int n0 = blockIdx.x * 128;
    const int lm = tid >> 1;
    const int lk = (tid & 1) << 2;
    const int tx = tid & 15;
    const int ty = tid >> 4;

    ull acc2[8][4] = {};

    float4 a4 = *(const float4*)(A + (size_t)(m0 + lm) * DD + lk);
    float4 w4 = *(const float4*)(W + (size_t)(n0 + lm) * DD + lk);

    for (int k0 = 0; k0 < DD; k0 += 8) {
        __syncthreads();
        As[lk + 0][lm] = a4.x; As[lk + 1][lm] = a4.y;
        As[lk + 2][lm] = a4.z; As[lk + 3][lm] = a4.w;
        Bs[lk + 0][lm] = w4.x; Bs[lk + 1][lm] = w4.y;
        Bs[lk + 2][lm] = w4.z; Bs[lk + 3][lm] = w4.w;
        __syncthreads();
        if (k0 + 8 < DD) {
            a4 = *(const float4*)(A + (size_t)(m0 + lm) * DD + k0 + 8 + lk);
            w4 = *(const float4*)(W + (size_t)(n0 + lm) * DD + k0 + 8 + lk);
        }
#pragma unroll
        for (int kk = 0; kk < 8; kk++) {
            float4 av0 = *(const float4*)&As[kk][ty * 8];
            float4 av1 = *(const float4*)&As[kk][ty * 8 + 4];
            float4 bv0 = *(const float4*)&Bs[kk][tx * 8];
            float4 bv1 = *(const float4*)&Bs[kk][tx * 8 + 4];
            ull b0 = pack2(bv0.x, bv0.y);
            ull b1 = pack2(bv0.z, bv0.w);
            ull b2 = pack2(bv1.x, bv1.y);
            ull b3 = pack2(bv1.z, bv1.w);
            float am[8] = {av0.x, av0.y, av0.z, av0.w, av1.x, av1.y, av1.z, av1.w};
#pragma unroll
            for (int i2 = 0; i2 < 8; i2++) {
                ull aa = pack2(am[i2], am[i2]);
                acc2[i2][0] = fma2(aa, b0, acc2[i2][0]);
                acc2[i2][1] = fma2(aa, b1, acc2[i2][1]);
                acc2[i2][2] = fma2(aa, b2, acc2[i2][2]);
                acc2[i2][3] = fma2(aa, b3, acc2[i2][3]);
            }
        }
    }

    float4 bb0 = *(const float4*)(bias + n0 + tx * 8);
    float4 bb1 = *(const float4*)(bias + n0 + tx * 8 + 4);
    float bb[8] = {bb0.x, bb0.y, bb0.z, bb0.w, bb1.x, bb1.y, bb1.z, bb1.w};
#pragma unroll
    for (int i2 = 0; i2 < 8; i2++) {
        float r[8];
        unpack2(acc2[i2][0], r[0], r[1]);
        unpack2(acc2[i2][1], r[2], r[3]);
        unpack2(acc2[i2][2], r[4], r[5]);
        unpack2(acc2[i2][3], r[6], r[7]);
        float4 o0, o1;
#pragma unroll
        for (int j2 = 0; j2 < 8; j2++) {
            float v = r[j2] + bb[j2];
            if (ACT == 1) v = 1.0f / (1.0f + expf(-v));
            else if (ACT == 2) v = expf(v);
            if (j2 < 4) (&o0.x)[j2] = v; else (&o1.x)[j2 - 4] = v;
        }
        float* dst = out + (size_t)(m0 + ty * 8 + i2) * DD + n0 + tx * 8;
        *(float4*)dst = o0;
        *(float4*)(dst + 4) = o1;
    }
}

// ---------------------------------------------------------------------------
// n-scan: 64 blocks x 32 threads (2048 independent chains)
// ---------------------------------------------------------------------------
__global__ void nscan_kernel()
{
    const int cid = blockIdx.x * 32 + threadIdx.x;   // 0..2047
    const int b = cid >> 8;
    const int j = cid & 255;
    const size_t base = (size_t)b * SS * DD + j;
    float n = 0.0f;
#pragma unroll 8
    for (int t = 0; t < SS; t++) {
        size_t o = base + (size_t)t * DD;
        n = fmaf(g_f[o], n, g_i[o] * g_k[o]);
        g_n[o] = n;
    }
}

// ---------------------------------------------------------------------------
// den
// ---------------------------------------------------------------------------
__global__ void den_kernel()
{
    const int warp = threadIdx.x >> 5;
    const int lane = threadIdx.x & 31;
    const int m = blockIdx.x * 8 + warp;
    const size_t base = (size_t)m * DD + lane * 8;
    float4 na = *(const float4*)(g_n + base);
    float4 nb = *(const float4*)(g_n + base + 4);
    float4 qa = *(const float4*)(g_q + base);
    float4 qb = *(const float4*)(g_q + base + 4);
    float d = na.x * qa.x + na.y * qa.y + na.z * qa.z + na.w * qa.w
            + nb.x * qb.x + nb.y * qb.y + nb.z * qb.z + nb.w * qb.w;
#pragma unroll
    for (int o = 16; o; o >>= 1) d += __shfl_xor_sync(0xffffffffu, d, o);
    if (lane == 0) g_inv[m] = 1.0f / fmaxf(fabsf(d), 1.0f);
}

// ---------------------------------------------------------------------------
// Chunkwise C-scan, register-tiled + warp-specialized. Chunk=16, CTA=256 thr.
//  phaseA (16 thr): G[u][i]=prod f, a[u][i]=i*v/G
//  warps 0-3:  dots GEMM  P[t][j]=k_j.q_t, CQ[t][j]=C[j,:].q_t
//              lane(mg=tid&15, ng=tid>>4): 2x2 tile rows{k_mg,C_mg} x t{ng,ng+8}
//  warps 4-7:  update-acc (concurrent; reads only): thread(i,jg) owns 32 cols:
//              acc = C[i,cols] + sum_s a[s][i] k_s[cols]; post-barrier: *=G15,
//              write back.
//  combine (256 thr): h_t[i] = G[t][i]*(CQ[t][i]+sum_{s<=t}a[s][i]P[t][s])*inv
// ---------------------------------------------------------------------------
constexpr int TC = 16;
constexpr int LDR = 260;

struct CScanSmem {
    float k[2][TC][LDR];
    float q[2][TC][LDR];
    float C[TC][LDR];
    float g[2][TC][48];
    float d[2][TC];
    float G[TC][16];
    float a[TC][16];
    float P[TC][TC];
    float CQ[TC][16];
};
constexpr int CSMEM = sizeof(CScanSmem);

__global__ void __launch_bounds__(256, 1) cscan_kernel()
{
    extern __shared__ char smem_raw[];
    CScanSmem* S = (CScanSmem*)smem_raw;

    const int b    = blockIdx.x >> 4;
    const int grp  = blockIdx.x & 15;
    const int tid  = threadIdx.x;
    const size_t mb = (size_t)b * SS * DD;
    const int rowb = grp * 16;

    const uint32_t sk_u = (uint32_t)__cvta_generic_to_shared(&S->k[0][0][0]);
    const uint32_t sq_u = (uint32_t)__cvta_generic_to_shared(&S->q[0][0][0]);
    const uint32_t sg_u = (uint32_t)__cvta_generic_to_shared(&S->g[0][0][0]);
    const uint32_t sd_u = (uint32_t)__cvta_generic_to_shared(&S->d[0][0]);

    auto fill = [&](int st, int tt) {
#pragma unroll
        for (int j = 0; j < 4; j++) {
            int idx = tid + j * 256;
            int t = idx >> 6, gr = idx & 63;
            cp_async16(sk_u + (uint32_t)(((st * TC + t) * LDR + gr * 4) * 4),
                       g_k + mb + (size_t)(tt + t) * DD + gr * 4);
        }
#pragma unroll
        for (int j = 0; j < 4; j++) {
            int idx = tid + j * 256;
            int t = idx >> 6, gr = idx & 63;
            cp_async16(sq_u + (uint32_t)(((st * TC + t) * LDR + gr * 4) * 4),
                       g_q + mb + (size_t)(tt + t) * DD + gr * 4);
        }
        if (tid < 192) {
            int t = tid / 12, gi = tid % 12;
            int gate = gi >> 2, part = gi & 3;
            const float* src =
                (gate == 0 ? g_f : (gate == 1 ? g_i : g_q))   // v == q
                + mb + (size_t)(tt + t) * DD + rowb + part * 4;
            cp_async16(sg_u + (uint32_t)(((st * TC + t) * 48 + gate * 16 + part * 4) * 4),
                       src);
        }
        if (tid < TC)
            cp_async4(sd_u + (uint32_t)((st * TC + tid) * 4),
                      g_inv + b * SS + tt + tid);
    };

    // zero C
    for (int idx = tid; idx < TC * LDR; idx += 256)
        (&S->C[0][0])[idx] = 0.0f;

    fill(0, 0); cp_commit();
    fill(1, TC); cp_commit();

    // precomputed per-thread roles
    const int mg = tid & 15;          // dots: A-row pair (k_mg, C_mg)
    const int ng = tid >> 4;          // dots: t pair (ng, ng+8); valid tid<128
    const int ui = (tid - 128) >> 3;  // update: row i; valid tid>=128
    const int uj = tid & 7;           // update: col group (32 cols)

    for (int blk = 0; blk < SS / TC; blk++) {
        const int st = blk & 1;
        cp_wait<1>();
        __syncthreads();                       // BAR0

        // ---- phase A: gate prefix products ----
        if (tid < 16) {
            float g = 1.0f;
#pragma unroll
            for (int u = 0; u < TC; u++) {
                float f  = S->g[st][u][tid];
                float ig = S->g[st][u][16 + tid];
                float vg = S->g[st][u][32 + tid];
                g *= f;
                S->G[u][tid] = g;
                S->a[u][tid] = __fdividef(ig * vg, g);
            }
        }
        __syncthreads();                       // BAR1

        ull uacc[16];                          // update accumulators (live only tid>=128)
        if (tid < 128) {
            // ---- dots: 2x2 register tile over K=256 ----
            const float* kr = &S->k[st][mg][0];
            const float* Cr = &S->C[mg][0];
            const float* q0r = &S->q[st][ng][0];
            const float* q1r = &S->q[st][ng + 8][0];
            ull aP0 = 0, bP0 = 0, aP1 = 0, bP1 = 0;
            ull aQ0 = 0, bQ0 = 0, aQ1 = 0, bQ1 = 0;
#pragma unroll 8
            for (int c = 0; c < DD; c += 4) {
                float4 A0 = *(const float4*)(kr + c);
                float4 A1 = *(const float4*)(Cr + c);
                float4 B0 = *(const float4*)(q0r + c);
                float4 B1 = *(const float4*)(q1r + c);
                ull a0xy = pack2(A0.x, A0.y), a0zw = pack2(A0.z, A0.w);
                ull a1xy = pack2(A1.x, A1.y), a1zw = pack2(A1.z, A1.w);
                ull b0xy = pack2(B0.x, B0.y), b0zw = pack2(B0.z, B0.w);
                ull b1xy = pack2(B1.x, B1.y), b1zw = pack2(B1.z, B1.w);
                aP0 = fma2(a0xy, b0xy, aP0); bP0 = fma2(a0zw, b0zw, bP0);
                aP1 = fma2(a0xy, b1xy, aP1); bP1 = fma2(a0zw, b1zw, bP1);
                aQ0 = fma2(a1xy, b0xy, aQ0); bQ0 = fma2(a1zw, b0zw, bQ0);
                aQ1 = fma2(a1xy, b1xy, aQ1); bQ1 = fma2(a1zw, b1zw, bQ1);
            }
            S->P[ng][mg]      = hsum2(add2(aP0, bP0));
            S->P[ng + 8][mg]  = hsum2(add2(aP1, bP1));
            S->CQ[ng][mg]     = hsum2(add2(aQ0, bQ0));
            S->CQ[ng + 8][mg] = hsum2(add2(aQ1, bQ1));
        } else {
            // ---- update-accumulate (reads old C + k; no writes yet) ----
            const float* Cr = &S->C[ui][uj * 32];
#pragma unroll
            for (int m = 0; m < 8; m++) {
                float4 c4 = *(const float4*)(Cr + 4 * m);
                uacc[2 * m]     = pack2(c4.x, c4.y);
                uacc[2 * m + 1] = pack2(c4.z, c4.w);
            }
#pragma unroll 4
            for (int s = 0; s < TC; s++) {
                float as = S->a[s][ui];
                ull as2 = pack2(as, as);
                const float* krs = &S->k[st][s][uj * 32];
#pragma unroll
                for (int m = 0; m < 8; m++) {
                    float4 k4 = *(const float4*)(krs + 4 * m);
                    uacc[2 * m]     = fma2(as2, pack2(k4.x, k4.y), uacc[2 * m]);
                    uacc[2 * m + 1] = fma2(as2, pack2(k4.z, k4.w), uacc[2 * m + 1]);
                }
            }
        }
        __syncthreads();                       // BAR2: dots done reading C, P/CQ ready

        if (tid >= 128) {
            // ---- C write-back with renorm ----
            float ge = S->G[TC - 1][ui];
            ull g2 = pack2(ge, ge);
            float* Cw = &S->C[ui][uj * 32];
#pragma unroll
            for (int m = 0; m < 8; m++) {
                float4 c4;
                unpack2(mul2(uacc[2 * m], g2), c4.x, c4.y);
                unpack2(mul2(uacc[2 * m + 1], g2), c4.z, c4.w);
                *(float4*)(Cw + 4 * m) = c4;
            }
        }

        // ---- combine + store ----
        {
            const int t = tid >> 4, i = tid & 15;
            float num = S->CQ[t][i];
            for (int s = 0; s <= t; s++)
                num = fmaf(S->a[s][i], S->P[t][s], num);
            float h = S->G[t][i] * num * S->d[st][t];
            g_h[mb + (size_t)(blk * TC + t) * DD + rowb + i] = h;
        }
        __syncthreads();                       // BAR3

        const int nb = blk + 2;
        if (nb < SS / TC) fill(st, nb * TC);
        cp_commit();
    }
}

// ---------------------------------------------------------------------------
// Launch
// ---------------------------------------------------------------------------
extern "C" void kernel_launch(void* const* d_in, const int* in_sizes, int n_in,
                              void* d_out, int out_size)
{
    const float* x   = (const float*)d_in[0];
    const float* Wq  = (const float*)d_in[1];
    const float* bq  = (const float*)d_in[2];
    const float* Wk  = (const float*)d_in[3];
    const float* bkk = (const float*)d_in[4];
    // d_in[5] = Wv, d_in[6] = bv — unused (reference uses W_q for v)
    const float* Wf  = (const float*)d_in[7];
    const float* bff = (const float*)d_in[8];
    const float* Wi  = (const float*)d_in[9];
    const float* bii = (const float*)d_in[10];
    const float* Wo  = (const float*)d_in[11];
    const float* bo  = (const float*)d_in[12];
    float* out = (float*)d_out;

    float *pq, *pk, *pf, *pi, *ph;
    cudaGetSymbolAddress((void**)&pq, g_q);
    cudaGetSymbolAddress((void**)&pk, g_k);
    cudaGetSymbolAddress((void**)&pf, g_f);
    cudaGetSymbolAddress((void**)&pi, g_i);
    cudaGetSymbolAddress((void**)&ph, g_h);

    static int smem_set = 0;
    if (!smem_set) {
        cudaFuncSetAttribute(cscan_kernel,
                             cudaFuncAttributeMaxDynamicSharedMemorySize, CSMEM);
        smem_set = 1;
    }

    dim3 ggrid(DD / 128, MTOT / 128);   // (2, 64) = 128 CTAs

    gemm_kernel<0><<<ggrid, 256>>>(x, Wq, bq, pq);
    gemm_kernel<0><<<ggrid, 256>>>(x, Wk, bkk, pk);
    gemm_kernel<1><<<ggrid, 256>>>(x, Wf, bff, pf);
    gemm_kernel<2><<<ggrid, 256>>>(x, Wi, bii, pi);

    nscan_kernel<<<64, 32>>>();
    den_kernel<<<MTOT / 8, 256>>>();
    cscan_kernel<<<BB * 16, 256, CSMEM>>>();

    gemm_kernel<0><<<ggrid, 256>>>(ph, Wo, bo, out);
}

// round 10
// speedup vs baseline: 1.7793x; 1.7793x over previous
#include <cuda_runtime.h>
#include <math.h>
#include <stdint.h>

// Problem dims
constexpr int BB = 8;
constexpr int SS = 1024;
constexpr int DD = 256;
constexpr int MTOT = BB * SS;          // 8192
constexpr int TC = 16;                 // chunk length
constexpr int CH = SS / TC;            // 64 chunks
constexpr int LDR = 260;               // padded smem row stride

// Scratch (device globals — no cudaMalloc allowed)
__device__ float g_q[MTOT * DD];
__device__ float g_k[MTOT * DD];
__device__ float g_f[MTOT * DD];
__device__ float g_i[MTOT * DD];
__device__ float g_n[MTOT * DD];
__device__ float g_h[MTOT * DD];
__device__ float g_inv[MTOT + 64];
// chunkwise scan scratch
__device__ float g_U [BB * CH * DD * DD];   // 128 MB: per-chunk rank-16 update
__device__ float g_Cs[BB * CH * DD * DD];   // 128 MB: C state at chunk start
__device__ float g_G [BB * CH * TC * DD];   // gate prefix products
__device__ float g_a [BB * CH * TC * DD];   // normalized input coeffs
__device__ float g_P [BB * CH * TC * TC];   // k_s . q_t per chunk

typedef unsigned long long ull;

// ---- f32x2 helpers ----
__device__ __forceinline__ ull pack2(float lo, float hi) {
    ull r; asm("mov.b64 %0, {%1, %2};" : "=l"(r) : "f"(lo), "f"(hi)); return r;
}
__device__ __forceinline__ ull fma2(ull a, ull b, ull c) {
    ull d; asm("fma.rn.f32x2 %0, %1, %2, %3;" : "=l"(d) : "l"(a), "l"(b), "l"(c)); return d;
}
__device__ __forceinline__ ull mul2(ull a, ull b) {
    ull d; asm("mul.rn.f32x2 %0, %1, %2;" : "=l"(d) : "l"(a), "l"(b)); return d;
}
__device__ __forceinline__ ull add2(ull a, ull b) {
    ull d; asm("add.rn.f32x2 %0, %1, %2;" : "=l"(d) : "l"(a), "l"(b)); return d;
}
__device__ __forceinline__ void unpack2(ull v, float& lo, float& hi) {
    asm("mov.b64 {%0, %1}, %2;" : "=f"(lo), "=f"(hi) : "l"(v));
}
__device__ __forceinline__ float hsum2(ull v) {
    float lo, hi; unpack2(v, lo, hi); return lo + hi;
}

// ---------------------------------------------------------------------------
// Fused input GEMM: z selects (Wq,Wk,Wf,Wi); act: z==2 sigmoid, z==3 exp.
// 128x128 tile, BK=8, 256 thr, 8x8/thread, f32x2. grid (2,64,4).
// ---------------------------------------------------------------------------
__global__ void __launch_bounds__(256) gemm4_kernel(
    const float* __restrict__ x,
    const float* __restrict__ W0, const float* __restrict__ b0,
    const float* __restrict__ W1, const float* __restrict__ b1,
    const float* __restrict__ W2, const float* __restrict__ b2,
    const float* __restrict__ W3, const float* __restrict__ b3,
    float* __restrict__ o0, float* __restrict__ o1,
    float* __restrict__ o2, float* __restrict__ o3)
{
    __shared__ float As[8][132];
    __shared__ float Bs[8][132];

    const int z = blockIdx.z;
    const float* W = (z == 0) ? W0 : (z == 1) ? W1 : (z == 2) ? W2 : W3;
    const float* bias = (z == 0) ? b0 : (z == 1) ? b1 : (z == 2) ? b2 : b3;
    float* out = (z == 0) ? o0 : (z == 1) ? o1 : (z == 2) ? o2 : o3;

    const int tid = threadIdx.x;
    const int m0 = blockIdx.y * 128;
    const int n0 = blockIdx.x * 128;
    const int lm = tid >> 1;
    const int lk = (tid & 1) << 2;
    const int tx = tid & 15;
    const int ty = tid >> 4;

    ull acc2[8][4] = {};

    float4 a4 = *(const float4*)(x + (size_t)(m0 + lm) * DD + lk);
    float4 w4 = *(const float4*)(W + (size_t)(n0 + lm) * DD + lk);

    for (int k0 = 0; k0 < DD; k0 += 8) {
        __syncthreads();
        As[lk + 0][lm] = a4.x; As[lk + 1][lm] = a4.y;
        As[lk + 2][lm] = a4.z; As[lk + 3][lm] = a4.w;
        Bs[lk + 0][lm] = w4.x; Bs[lk + 1][lm] = w4.y;
        Bs[lk + 2][lm] = w4.z; Bs[lk + 3][lm] = w4.w;
        __syncthreads();
        if (k0 + 8 < DD) {
            a4 = *(const float4*)(x + (size_t)(m0 + lm) * DD + k0 + 8 + lk);
            w4 = *(const float4*)(W + (size_t)(n0 + lm) * DD + k0 + 8 + lk);
        }
#pragma unroll
        for (int kk = 0; kk < 8; kk++) {
            float4 av0 = *(const float4*)&As[kk][ty * 8];
            float4 av1 = *(const float4*)&As[kk][ty * 8 + 4];
            float4 bv0 = *(const float4*)&Bs[kk][tx * 8];
            float4 bv1 = *(const float4*)&Bs[kk][tx * 8 + 4];
            ull b0p = pack2(bv0.x, bv0.y);
            ull b1p = pack2(bv0.z, bv0.w);
            ull b2p = pack2(bv1.x, bv1.y);
            ull b3p = pack2(bv1.z, bv1.w);
            float am[8] = {av0.x, av0.y, av0.z, av0.w, av1.x, av1.y, av1.z, av1.w};
#pragma unroll
            for (int i2 = 0; i2 < 8; i2++) {
                ull aa = pack2(am[i2], am[i2]);
                acc2[i2][0] = fma2(aa, b0p, acc2[i2][0]);
                acc2[i2][1] = fma2(aa, b1p, acc2[i2][1]);
                acc2[i2][2] = fma2(aa, b2p, acc2[i2][2]);
                acc2[i2][3] = fma2(aa, b3p, acc2[i2][3]);
            }
        }
    }

    float4 bb0 = *(const float4*)(bias + n0 + tx * 8);
    float4 bb1 = *(const float4*)(bias + n0 + tx * 8 + 4);
    float bb[8] = {bb0.x, bb0.y, bb0.z, bb0.w, bb1.x, bb1.y, bb1.z, bb1.w};
#pragma unroll
    for (int i2 = 0; i2 < 8; i2++) {
        float r[8];
        unpack2(acc2[i2][0], r[0], r[1]);
        unpack2(acc2[i2][1], r[2], r[3]);
        unpack2(acc2[i2][2], r[4], r[5]);
        unpack2(acc2[i2][3], r[6], r[7]);
        float4 q0, q1;
#pragma unroll
        for (int j2 = 0; j2 < 8; j2++) {
            float v = r[j2] + bb[j2];
            if (z == 2) v = 1.0f / (1.0f + expf(-v));
            else if (z == 3) v = expf(v);
            if (j2 < 4) (&q0.x)[j2] = v; else (&q1.x)[j2 - 4] = v;
        }
        float* dst = out + (size_t)(m0 + ty * 8 + i2) * DD + n0 + tx * 8;
        *(float4*)dst = q0;
        *(float4*)(dst + 4) = q1;
    }
}

// ---------------------------------------------------------------------------
// Output GEMM (no activation)
// ---------------------------------------------------------------------------
__global__ void __launch_bounds__(256) gemm_out_kernel(
    const float* __restrict__ A, const float* __restrict__ W,
    const float* __restrict__ bias, float* __restrict__ out)
{
    __shared__ float As[8][132];
    __shared__ float Bs[8][132];

    const int tid = threadIdx.x;
    const int m0 = blockIdx.y * 128;
    const int n0 = blockIdx.x * 128;
    const int lm = tid >> 1;
    const int lk = (tid & 1) << 2;
    const int tx = tid & 15;
    const int ty = tid >> 4;

    ull acc2[8][4] = {};

    float4 a4 = *(const float4*)(A + (size_t)(m0 + lm) * DD + lk);
    float4 w4 = *(const float4*)(W + (size_t)(n0 + lm) * DD + lk);

    for (int k0 = 0; k0 < DD; k0 += 8) {
        __syncthreads();
        As[lk + 0][lm] = a4.x; As[lk + 1][lm] = a4.y;
        As[lk + 2][lm] = a4.z; As[lk + 3][lm] = a4.w;
        Bs[lk + 0][lm] = w4.x; Bs[lk + 1][lm] = w4.y;
        Bs[lk + 2][lm] = w4.z; Bs[lk + 3][lm] = w4.w;
        __syncthreads();
        if (k0 + 8 < DD) {
            a4 = *(const float4*)(A + (size_t)(m0 + lm) * DD + k0 + 8 + lk);
            w4 = *(const float4*)(W + (size_t)(n0 + lm) * DD + k0 + 8 + lk);
        }
#pragma unroll
        for (int kk = 0; kk < 8; kk++) {
            float4 av0 = *(const float4*)&As[kk][ty * 8];
            float4 av1 = *(const float4*)&As[kk][ty * 8 + 4];
            float4 bv0 = *(const float4*)&Bs[kk][tx * 8];
            float4 bv1 = *(const float4*)&Bs[kk][tx * 8 + 4];
            ull b0p = pack2(bv0.x, bv0.y);
            ull b1p = pack2(bv0.z, bv0.w);
            ull b2p = pack2(bv1.x, bv1.y);
            ull b3p = pack2(bv1.z, bv1.w);
            float am[8] = {av0.x, av0.y, av0.z, av0.w, av1.x, av1.y, av1.z, av1.w};
#pragma unroll
            for (int i2 = 0; i2 < 8; i2++) {
                ull aa = pack2(am[i2], am[i2]);
                acc2[i2][0] = fma2(aa, b0p, acc2[i2][0]);
                acc2[i2][1] = fma2(aa, b1p, acc2[i2][1]);
                acc2[i2][2] = fma2(aa, b2p, acc2[i2][2]);
                acc2[i2][3] = fma2(aa, b3p, acc2[i2][3]);
            }
        }
    }

    float4 bb0 = *(const float4*)(bias + n0 + tx * 8);
    float4 bb1 = *(const float4*)(bias + n0 + tx * 8 + 4);
    float bb[8] = {bb0.x, bb0.y, bb0.z, bb0.w, bb1.x, bb1.y, bb1.z, bb1.w};
#pragma unroll
    for (int i2 = 0; i2 < 8; i2++) {
        float r[8];
        unpack2(acc2[i2][0], r[0], r[1]);
        unpack2(acc2[i2][1], r[2], r[3]);
        unpack2(acc2[i2][2], r[4], r[5]);
        unpack2(acc2[i2][3], r[6], r[7]);
        float4 q0, q1;
#pragma unroll
        for (int j2 = 0; j2 < 8; j2++) {
            float v = r[j2] + bb[j2];
            if (j2 < 4) (&q0.x)[j2] = v; else (&q1.x)[j2 - 4] = v;
        }
        float* dst = out + (size_t)(m0 + ty * 8 + i2) * DD + n0 + tx * 8;
        *(float4*)dst = q0;
        *(float4*)(dst + 4) = q1;
    }
}

// ---------------------------------------------------------------------------
// n-scan: 2048 independent chains
// ---------------------------------------------------------------------------
__global__ void nscan_kernel()
{
    const int cid = blockIdx.x * 32 + threadIdx.x;
    const int b = cid >> 8;
    const int j = cid & 255;
    const size_t base = (size_t)b * SS * DD + j;
    float n = 0.0f;
#pragma unroll 8
    for (int t = 0; t < SS; t++) {
        size_t o = base + (size_t)t * DD;
        n = fmaf(g_f[o], n, g_i[o] * g_k[o]);
        g_n[o] = n;
    }
}

// ---------------------------------------------------------------------------
// den: inv_den[b,t] = 1 / max(|n_t . q_t|, 1)
// ---------------------------------------------------------------------------
__global__ void den_kernel()
{
    const int warp = threadIdx.x >> 5;
    const int lane = threadIdx.x & 31;
    const int m = blockIdx.x * 8 + warp;
    const size_t base = (size_t)m * DD + lane * 8;
    float4 na = *(const float4*)(g_n + base);
    float4 nb = *(const float4*)(g_n + base + 4);
    float4 qa = *(const float4*)(g_q + base);
    float4 qb = *(const float4*)(g_q + base + 4);
    float d = na.x * qa.x + na.y * qa.y + na.z * qa.z + na.w * qa.w
            + nb.x * qb.x + nb.y * qb.y + nb.z * qb.z + nb.w * qb.w;
#pragma unroll
    for (int o = 16; o; o >>= 1) d += __shfl_xor_sync(0xffffffffu, d, o);
    if (lane == 0) g_inv[m] = 1.0f / fmaxf(fabsf(d), 1.0f);
}

// ---------------------------------------------------------------------------
// P1: per (b,chunk) — gates G/a, P = k.q^T, U = rank-16 chunk update.
// grid = 512 (b*64+m), 256 threads, ~50KB dynamic smem.
// ---------------------------------------------------------------------------
constexpr int P1_SMEM = (TC * LDR + TC * DD + TC * DD + DD) * 4;

__global__ void __launch_bounds__(256) p1_kernel()
{
    extern __shared__ float p1s[];
    float* sk   = p1s;                 // [TC][LDR]
    float* sq   = sk + TC * LDR;       // [TC][DD]
    float* sa   = sq + TC * DD;        // [TC][DD]
    float* sg15 = sa + TC * DD;        // [DD]

    const int bm = blockIdx.x;
    const int b = bm >> 6, m = bm & 63;
    const int tid = threadIdx.x;
    const size_t mb = (size_t)b * SS * DD;
    const int tt = m * TC;

    // load k,q into smem (k padded)
#pragma unroll
    for (int v = 0; v < 4; v++) {
        int idx = tid + v * 256;               // 0..1023 float4 granules
        int t = idx >> 6, gr = idx & 63;
        *(float4*)&sk[t * LDR + gr * 4] =
            *(const float4*)(g_k + mb + (size_t)(tt + t) * DD + gr * 4);
        *(float4*)&sq[t * DD + gr * 4] =
            *(const float4*)(g_q + mb + (size_t)(tt + t) * DD + gr * 4);
    }
    // gates: thread = channel i
    {
        const int i = tid;
        float g = 1.0f;
#pragma unroll
        for (int u = 0; u < TC; u++) {
            size_t o = mb + (size_t)(tt + u) * DD + i;
            float f = g_f[o], ii = g_i[o], vv = g_q[o];   // v == q
            g *= f;
            float av = __fdividef(ii * vv, g);
            sa[u * DD + i] = av;
            g_G[(size_t)(bm * TC + u) * DD + i] = g;
            g_a[(size_t)(bm * TC + u) * DD + i] = av;
        }
        sg15[i] = g;
    }
    __syncthreads();

    // P[t][j] = k_j . q_t
    {
        const int t = tid >> 4, j = tid & 15;
        ull acc0 = 0, acc1 = 0;
#pragma unroll 8
        for (int c = 0; c < DD; c += 4) {
            float4 k4 = *(const float4*)&sk[j * LDR + c];
            float4 q4 = *(const float4*)&sq[t * DD + c];
            acc0 = fma2(pack2(k4.x, k4.y), pack2(q4.x, q4.y), acc0);
            acc1 = fma2(pack2(k4.z, k4.w), pack2(q4.z, q4.w), acc1);
        }
        g_P[(size_t)bm * TC * TC + t * TC + j] = hsum2(add2(acc0, acc1));
    }

    // U[i][c] = g15[i] * sum_s a[s][i] * k[s][c]   (thread = column c)
    {
        const int c = tid;
        float kv[TC];
#pragma unroll
        for (int s = 0; s < TC; s++) kv[s] = sk[s * LDR + c];
        float* Ubase = g_U + (size_t)bm * DD * DD + c;
#pragma unroll 2
        for (int ig = 0; ig < DD; ig += 4) {
            ull a0 = 0, a1 = 0;
#pragma unroll
            for (int s = 0; s < TC; s++) {
                ull ks2 = pack2(kv[s], kv[s]);
                float4 av4 = *(const float4*)&sa[s * DD + ig];   // broadcast
                a0 = fma2(pack2(av4.x, av4.y), ks2, a0);
                a1 = fma2(pack2(av4.z, av4.w), ks2, a1);
            }
            float4 g4 = *(const float4*)&sg15[ig];
            float x0, x1, x2, x3;
            unpack2(mul2(a0, pack2(g4.x, g4.y)), x0, x1);
            unpack2(mul2(a1, pack2(g4.z, g4.w)), x2, x3);
            Ubase[(size_t)(ig + 0) * DD] = x0;
            Ubase[(size_t)(ig + 1) * DD] = x1;
            Ubase[(size_t)(ig + 2) * DD] = x2;
            Ubase[(size_t)(ig + 3) * DD] = x3;
        }
    }
}

// ---------------------------------------------------------------------------
// P2: chunk-level scan (only serial part): Cs_m = g15_{m-1}*Cs_{m-1} + U_{m-1}
// grid = 2048 (b*256+i), 256 threads = columns. Pure streaming.
// ---------------------------------------------------------------------------
__global__ void __launch_bounds__(256) p2_kernel()
{
    const int bi = blockIdx.x;
    const int b = bi >> 8, i = bi & 255;
    const int c = threadIdx.x;
    float Cs = 0.0f;
    for (int m = 0; m < CH; m++) {
        const int bm = b * CH + m;
        const size_t off = (size_t)bm * DD * DD + (size_t)i * DD + c;
        g_Cs[off] = Cs;
        float g15 = g_G[(size_t)(bm * TC + 15) * DD + i];
        Cs = fmaf(g15, Cs, g_U[off]);
    }
}

// ---------------------------------------------------------------------------
// P3: per (b,chunk,rowgroup) — CQ = Cs.q^T + triangular combine. Fully
// parallel over time. grid = 8192, 128 threads, ~35KB static smem.
// ---------------------------------------------------------------------------
struct P3Smem {
    float q[TC][LDR];
    float Cs[TC][LDR];
    float a[TC][16];
    float G[TC][16];
    float P[TC][TC];
    float inv[TC];
};

__global__ void __launch_bounds__(128) p3_kernel()
{
    __shared__ P3Smem S;
    const int blk = blockIdx.x;
    const int grp = blk & 15;
    const int bm = blk >> 4;
    const int b = bm >> 6, m = bm & 63;
    const int tid = threadIdx.x;
    const int rowb = grp * 16;
    const size_t mb = (size_t)b * SS * DD;
    const int tt = m * TC;

#pragma unroll
    for (int v = 0; v < 8; v++) {
        int idx = tid + v * 128;               // 0..1023 float4 granules
        int t = idx >> 6, gr = idx & 63;
        *(float4*)&S.q[t][gr * 4] =
            *(const float4*)(g_q + mb + (size_t)(tt + t) * DD + gr * 4);
        *(float4*)&S.Cs[t][gr * 4] =
            *(const float4*)(g_Cs + (size_t)bm * DD * DD + (size_t)(rowb + t) * DD + gr * 4);
    }
    {
        int u = tid >> 4, il = tid & 15;
        S.a[u][il]     = g_a[(size_t)(bm * TC + u) * DD + rowb + il];
        S.a[u + 8][il] = g_a[(size_t)(bm * TC + u + 8) * DD + rowb + il];
        S.G[u][il]     = g_G[(size_t)(bm * TC + u) * DD + rowb + il];
        S.G[u + 8][il] = g_G[(size_t)(bm * TC + u + 8) * DD + rowb + il];
        ((float*)S.P)[tid]       = g_P[(size_t)bm * 256 + tid];
        ((float*)S.P)[tid + 128] = g_P[(size_t)bm * 256 + tid + 128];
        if (tid < TC) S.inv[tid] = g_inv[b * SS + tt + tid];
    }
    __syncthreads();

    // CQ[t][i]: row mg = tid&15, col pair t = {nh, nh+8}, nh = tid>>4
    const int mg = tid & 15;
    const int nh = tid >> 4;
    ull c00 = 0, c01 = 0, c10 = 0, c11 = 0;
    const float* Cr = &S.Cs[mg][0];
    const float* q0 = &S.q[nh][0];
    const float* q1 = &S.q[nh + 8][0];
#pragma unroll 8
    for (int c = 0; c < DD; c += 4) {
        float4 C4 = *(const float4*)(Cr + c);
        float4 B0 = *(const float4*)(q0 + c);
        float4 B1 = *(const float4*)(q1 + c);
        ull cxy = pack2(C4.x, C4.y), czw = pack2(C4.z, C4.w);
        c00 = fma2(cxy, pack2(B0.x, B0.y), c00);
        c01 = fma2(czw, pack2(B0.z, B0.w), c01);
        c10 = fma2(cxy, pack2(B1.x, B1.y), c10);
        c11 = fma2(czw, pack2(B1.z, B1.w), c11);
    }
    float CQ0 = hsum2(add2(c00, c01));
    float CQ1 = hsum2(add2(c10, c11));

    // combine + store
    {
        float num0 = CQ0;
#pragma unroll
        for (int s = 0; s < TC; s++)
            if (s <= nh) num0 = fmaf(S.a[s][mg], S.P[nh][s], num0);
        g_h[mb + (size_t)(tt + nh) * DD + rowb + mg] =
            S.G[nh][mg] * num0 * S.inv[nh];

        const int t1 = nh + 8;
        float num1 = CQ1;
#pragma unroll
        for (int s = 0; s < TC; s++)
            if (s <= t1) num1 = fmaf(S.a[s][mg], S.P[t1][s], num1);
        g_h[mb + (size_t)(tt + t1) * DD + rowb + mg] =
            S.G[t1][mg] * num1 * S.inv[t1];
    }
}

// ---------------------------------------------------------------------------
// Launch
// ---------------------------------------------------------------------------
extern "C" void kernel_launch(void* const* d_in, const int* in_sizes, int n_in,
                              void* d_out, int out_size)
{
    const float* x   = (const float*)d_in[0];
    const float* Wq  = (const float*)d_in[1];
    const float* bq  = (const float*)d_in[2];
    const float* Wk  = (const float*)d_in[3];
    const float* bkk = (const float*)d_in[4];
    // d_in[5] = Wv, d_in[6] = bv — unused (reference uses W_q for v)
    const float* Wf  = (const float*)d_in[7];
    const float* bff = (const float*)d_in[8];
    const float* Wi  = (const float*)d_in[9];
    const float* bii = (const float*)d_in[10];
    const float* Wo  = (const float*)d_in[11];
    const float* bo  = (const float*)d_in[12];
    float* out = (float*)d_out;

    float *pq, *pk, *pf, *pi, *ph;
    cudaGetSymbolAddress((void**)&pq, g_q);
    cudaGetSymbolAddress((void**)&pk, g_k);
    cudaGetSymbolAddress((void**)&pf, g_f);
    cudaGetSymbolAddress((void**)&pi, g_i);
    cudaGetSymbolAddress((void**)&ph, g_h);

    static int attr_set = 0;
    if (!attr_set) {
        cudaFuncSetAttribute(p1_kernel,
                             cudaFuncAttributeMaxDynamicSharedMemorySize, P1_SMEM);
        attr_set = 1;
    }

    // 4 input projections fused: grid (2,64,4)
    gemm4_kernel<<<dim3(2, 64, 4), 256>>>(x, Wq, bq, Wk, bkk, Wf, bff, Wi, bii,
                                          pq, pk, pf, pi);

    nscan_kernel<<<64, 32>>>();
    den_kernel<<<MTOT / 8, 256>>>();

    p1_kernel<<<BB * CH, 256, P1_SMEM>>>();
    p2_kernel<<<BB * DD, 256>>>();
    p3_kernel<<<BB * CH * 16, 128>>>();

    gemm_out_kernel<<<dim3(2, 64), 256>>>(ph, Wo, bo, out);
}

// round 11
// speedup vs baseline: 1.9242x; 1.0814x over previous
#include <cuda_runtime.h>
#include <cuda_fp16.h>
#include <math.h>
#include <stdint.h>

// Problem dims
constexpr int BB = 8;
constexpr int SS = 1024;
constexpr int DD = 256;
constexpr int MTOT = BB * SS;          // 8192
constexpr int TC = 16;                 // chunk length
constexpr int CH = SS / TC;            // 64 chunks
constexpr int LDR = 260;               // padded smem row stride

// Scratch (device globals — no cudaMalloc allowed)
__device__ float g_q[MTOT * DD];
__device__ float g_k[MTOT * DD];
__device__ float g_f[MTOT * DD];
__device__ float g_i[MTOT * DD];
__device__ float g_n[MTOT * DD];
__device__ float g_h[MTOT * DD];
__device__ float g_inv[MTOT + 64];
// chunkwise scan scratch
__device__ __half g_Csh[(size_t)BB * CH * DD * DD];  // 64 MB: C at chunk start (fp16)
__device__ float g_G[BB * CH * TC * DD];             // gate prefix products
__device__ float g_a[BB * CH * TC * DD];             // normalized input coeffs
__device__ float g_P[BB * CH * TC * TC];             // k_s . q_t per chunk

typedef unsigned long long ull;

// ---- f32x2 helpers ----
__device__ __forceinline__ ull pack2(float lo, float hi) {
    ull r; asm("mov.b64 %0, {%1, %2};" : "=l"(r) : "f"(lo), "f"(hi)); return r;
}
__device__ __forceinline__ ull fma2(ull a, ull b, ull c) {
    ull d; asm("fma.rn.f32x2 %0, %1, %2, %3;" : "=l"(d) : "l"(a), "l"(b), "l"(c)); return d;
}
__device__ __forceinline__ ull mul2(ull a, ull b) {
    ull d; asm("mul.rn.f32x2 %0, %1, %2;" : "=l"(d) : "l"(a), "l"(b)); return d;
}
__device__ __forceinline__ ull add2(ull a, ull b) {
    ull d; asm("add.rn.f32x2 %0, %1, %2;" : "=l"(d) : "l"(a), "l"(b)); return d;
}
__device__ __forceinline__ void unpack2(ull v, float& lo, float& hi) {
    asm("mov.b64 {%0, %1}, %2;" : "=f"(lo), "=f"(hi) : "l"(v));
}
__device__ __forceinline__ float hsum2(ull v) {
    float lo, hi; unpack2(v, lo, hi); return lo + hi;
}
__device__ __forceinline__ uint32_t f2_to_h2(float lo, float hi) {
    __half2 h = __floats2half2_rn(lo, hi);
    return *(uint32_t*)&h;
}

// ---- cp.async helpers ----
__device__ __forceinline__ void cp_async16(uint32_t saddr, const void* gptr) {
    asm volatile("cp.async.ca.shared.global [%0], [%1], 16;" :: "r"(saddr), "l"(gptr));
}
__device__ __forceinline__ void cp_commit() { asm volatile("cp.async.commit_group;"); }
template <int N>
__device__ __forceinline__ void cp_wait() {
    asm volatile("cp.async.wait_group %0;" :: "n"(N));
}

// ---------------------------------------------------------------------------
// Fused input GEMM (unchanged): z selects (Wq,Wk,Wf,Wi); grid (2,64,4).
// ---------------------------------------------------------------------------
__global__ void __launch_bounds__(256) gemm4_kernel(
    const float* __restrict__ x,
    const float* __restrict__ W0, const float* __restrict__ b0,
    const float* __restrict__ W1, const float* __restrict__ b1,
    const float* __restrict__ W2, const float* __restrict__ b2,
    const float* __restrict__ W3, const float* __restrict__ b3,
    float* __restrict__ o0, float* __restrict__ o1,
    float* __restrict__ o2, float* __restrict__ o3)
{
    __shared__ float As[8][132];
    __shared__ float Bs[8][132];

    const int z = blockIdx.z;
    const float* W = (z == 0) ? W0 : (z == 1) ? W1 : (z == 2) ? W2 : W3;
    const float* bias = (z == 0) ? b0 : (z == 1) ? b1 : (z == 2) ? b2 : b3;
    float* out = (z == 0) ? o0 : (z == 1) ? o1 : (z == 2) ? o2 : o3;

    const int tid = threadIdx.x;
    const int m0 = blockIdx.y * 128;
    const int n0 = blockIdx.x * 128;
    const int lm = tid >> 1;
    const int lk = (tid & 1) << 2;
    const int tx = tid & 15;
    const int ty = tid >> 4;

    ull acc2[8][4] = {};

    float4 a4 = *(const float4*)(x + (size_t)(m0 + lm) * DD + lk);
    float4 w4 = *(const float4*)(W + (size_t)(n0 + lm) * DD + lk);

    for (int k0 = 0; k0 < DD; k0 += 8) {
        __syncthreads();
        As[lk + 0][lm] = a4.x; As[lk + 1][lm] = a4.y;
        As[lk + 2][lm] = a4.z; As[lk + 3][lm] = a4.w;
        Bs[lk + 0][lm] = w4.x; Bs[lk + 1][lm] = w4.y;
        Bs[lk + 2][lm] = w4.z; Bs[lk + 3][lm] = w4.w;
        __syncthreads();
        if (k0 + 8 < DD) {
            a4 = *(const float4*)(x + (size_t)(m0 + lm) * DD + k0 + 8 + lk);
            w4 = *(const float4*)(W + (size_t)(n0 + lm) * DD + k0 + 8 + lk);
        }
#pragma unroll
        for (int kk = 0; kk < 8; kk++) {
            float4 av0 = *(const float4*)&As[kk][ty * 8];
            float4 av1 = *(const float4*)&As[kk][ty * 8 + 4];
            float4 bv0 = *(const float4*)&Bs[kk][tx * 8];
            float4 bv1 = *(const float4*)&Bs[kk][tx * 8 + 4];
            ull b0p = pack2(bv0.x, bv0.y);
            ull b1p = pack2(bv0.z, bv0.w);
            ull b2p = pack2(bv1.x, bv1.y);
            ull b3p = pack2(bv1.z, bv1.w);
            float am[8] = {av0.x, av0.y, av0.z, av0.w, av1.x, av1.y, av1.z, av1.w};
#pragma unroll
            for (int i2 = 0; i2 < 8; i2++) {
                ull aa = pack2(am[i2], am[i2]);
                acc2[i2][0] = fma2(aa, b0p, acc2[i2][0]);
                acc2[i2][1] = fma2(aa, b1p, acc2[i2][1]);
                acc2[i2][2] = fma2(aa, b2p, acc2[i2][2]);
                acc2[i2][3] = fma2(aa, b3p, acc2[i2][3]);
            }
        }
    }

    float4 bb0 = *(const float4*)(bias + n0 + tx * 8);
    float4 bb1 = *(const float4*)(bias + n0 + tx * 8 + 4);
    float bb[8] = {bb0.x, bb0.y, bb0.z, bb0.w, bb1.x, bb1.y, bb1.z, bb1.w};
#pragma unroll
    for (int i2 = 0; i2 < 8; i2++) {
        float r[8];
        unpack2(acc2[i2][0], r[0], r[1]);
        unpack2(acc2[i2][1], r[2], r[3]);
        unpack2(acc2[i2][2], r[4], r[5]);
        unpack2(acc2[i2][3], r[6], r[7]);
        float4 q0, q1;
#pragma unroll
        for (int j2 = 0; j2 < 8; j2++) {
            float v = r[j2] + bb[j2];
            if (z == 2) v = 1.0f / (1.0f + expf(-v));
            else if (z == 3) v = expf(v);
            if (j2 < 4) (&q0.x)[j2] = v; else (&q1.x)[j2 - 4] = v;
        }
        float* dst = out + (size_t)(m0 + ty * 8 + i2) * DD + n0 + tx * 8;
        *(float4*)dst = q0;
        *(float4*)(dst + 4) = q1;
    }
}

// ---------------------------------------------------------------------------
// Output GEMM (unchanged)
// ---------------------------------------------------------------------------
__global__ void __launch_bounds__(256) gemm_out_kernel(
    const float* __restrict__ A, const float* __restrict__ W,
    const float* __restrict__ bias, float* __restrict__ out)
{
    __shared__ float As[8][132];
    __shared__ float Bs[8][132];

    const int tid = threadIdx.x;
    const int m0 = blockIdx.y * 128;
    const int n0 = blockIdx.x * 128;
    const int lm = tid >> 1;
    const int lk = (tid & 1) << 2;
    const int tx = tid & 15;
    const int ty = tid >> 4;

    ull acc2[8][4] = {};

    float4 a4 = *(const float4*)(A + (size_t)(m0 + lm) * DD + lk);
    float4 w4 = *(const float4*)(W + (size_t)(n0 + lm) * DD + lk);

    for (int k0 = 0; k0 < DD; k0 += 8) {
        __syncthreads();
        As[lk + 0][lm] = a4.x; As[lk + 1][lm] = a4.y;
        As[lk + 2][lm] = a4.z; As[lk + 3][lm] = a4.w;
        Bs[lk + 0][lm] = w4.x; Bs[lk + 1][lm] = w4.y;
        Bs[lk + 2][lm] = w4.z; Bs[lk + 3][lm] = w4.w;
        __syncthreads();
        if (k0 + 8 < DD) {
            a4 = *(const float4*)(A + (size_t)(m0 + lm) * DD + k0 + 8 + lk);
            w4 = *(const float4*)(W + (size_t)(n0 + lm) * DD + k0 + 8 + lk);
        }
#pragma unroll
        for (int kk = 0; kk < 8; kk++) {
            float4 av0 = *(const float4*)&As[kk][ty * 8];
            float4 av1 = *(const float4*)&As[kk][ty * 8 + 4];
            float4 bv0 = *(const float4*)&Bs[kk][tx * 8];
            float4 bv1 = *(const float4*)&Bs[kk][tx * 8 + 4];
            ull b0p = pack2(bv0.x, bv0.y);
            ull b1p = pack2(bv0.z, bv0.w);
            ull b2p = pack2(bv1.x, bv1.y);
            ull b3p = pack2(bv1.z, bv1.w);
            float am[8] = {av0.x, av0.y, av0.z, av0.w, av1.x, av1.y, av1.z, av1.w};
#pragma unroll
            for (int i2 = 0; i2 < 8; i2++) {
                ull aa = pack2(am[i2], am[i2]);
                acc2[i2][0] = fma2(aa, b0p, acc2[i2][0]);
                acc2[i2][1] = fma2(aa, b1p, acc2[i2][1]);
                acc2[i2][2] = fma2(aa, b2p, acc2[i2][2]);
                acc2[i2][3] = fma2(aa, b3p, acc2[i2][3]);
            }
        }
    }

    float4 bb0 = *(const float4*)(bias + n0 + tx * 8);
    float4 bb1 = *(const float4*)(bias + n0 + tx * 8 + 4);
    float bb[8] = {bb0.x, bb0.y, bb0.z, bb0.w, bb1.x, bb1.y, bb1.z, bb1.w};
#pragma unroll
    for (int i2 = 0; i2 < 8; i2++) {
        float r[8];
        unpack2(acc2[i2][0], r[0], r[1]);
        unpack2(acc2[i2][1], r[2], r[3]);
        unpack2(acc2[i2][2], r[4], r[5]);
        unpack2(acc2[i2][3], r[6], r[7]);
        float4 q0, q1;
#pragma unroll
        for (int j2 = 0; j2 < 8; j2++) {
            float v = r[j2] + bb[j2];
            if (j2 < 4) (&q0.x)[j2] = v; else (&q1.x)[j2 - 4] = v;
        }
        float* dst = out + (size_t)(m0 + ty * 8 + i2) * DD + n0 + tx * 8;
        *(float4*)dst = q0;
        *(float4*)(dst + 4) = q1;
    }
}

// ---------------------------------------------------------------------------
// n-scan + den (unchanged)
// ---------------------------------------------------------------------------
__global__ void nscan_kernel()
{
    const int cid = blockIdx.x * 32 + threadIdx.x;
    const int b = cid >> 8;
    const int j = cid & 255;
    const size_t base = (size_t)b * SS * DD + j;
    float n = 0.0f;
#pragma unroll 8
    for (int t = 0; t < SS; t++) {
        size_t o = base + (size_t)t * DD;
        n = fmaf(g_f[o], n, g_i[o] * g_k[o]);
        g_n[o] = n;
    }
}

__global__ void den_kernel()
{
    const int warp = threadIdx.x >> 5;
    const int lane = threadIdx.x & 31;
    const int m = blockIdx.x * 8 + warp;
    const size_t base = (size_t)m * DD + lane * 8;
    float4 na = *(const float4*)(g_n + base);
    float4 nb = *(const float4*)(g_n + base + 4);
    float4 qa = *(const float4*)(g_q + base);
    float4 qb = *(const float4*)(g_q + base + 4);
    float d = na.x * qa.x + na.y * qa.y + na.z * qa.z + na.w * qa.w
            + nb.x * qb.x + nb.y * qb.y + nb.z * qb.z + nb.w * qb.w;
#pragma unroll
    for (int o = 16; o; o >>= 1) d += __shfl_xor_sync(0xffffffffu, d, o);
    if (lane == 0) g_inv[m] = 1.0f / fmaxf(fabsf(d), 1.0f);
}

// ---------------------------------------------------------------------------
// P1-lite: per (b,chunk) — gates G/a and P = k.q^T only (no U).
// grid = 512, 256 threads.
// ---------------------------------------------------------------------------
__global__ void __launch_bounds__(256) p1_kernel()
{
    __shared__ float sk[TC][LDR];
    __shared__ float sq[TC][DD];

    const int bm = blockIdx.x;
    const int b = bm >> 6, m = bm & 63;
    const int tid = threadIdx.x;
    const size_t mb = (size_t)b * SS * DD;
    const int tt = m * TC;

#pragma unroll
    for (int v = 0; v < 4; v++) {
        int idx = tid + v * 256;
        int t = idx >> 6, gr = idx & 63;
        *(float4*)&sk[t][gr * 4] =
            *(const float4*)(g_k + mb + (size_t)(tt + t) * DD + gr * 4);
        *(float4*)&sq[t][gr * 4] =
            *(const float4*)(g_q + mb + (size_t)(tt + t) * DD + gr * 4);
    }
    // gates: thread = channel i
    {
        const int i = tid;
        float g = 1.0f;
#pragma unroll
        for (int u = 0; u < TC; u++) {
            size_t o = mb + (size_t)(tt + u) * DD + i;
            float f = g_f[o], ii = g_i[o], vv = g_q[o];   // v == q
            g *= f;
            float av = __fdividef(ii * vv, g);
            g_G[(size_t)(bm * TC + u) * DD + i] = g;
            g_a[(size_t)(bm * TC + u) * DD + i] = av;
        }
    }
    __syncthreads();

    // P[t][j] = k_j . q_t
    {
        const int t = tid >> 4, j = tid & 15;
        ull acc0 = 0, acc1 = 0;
#pragma unroll 8
        for (int c = 0; c < DD; c += 4) {
            float4 k4 = *(const float4*)&sk[j][c];
            float4 q4 = *(const float4*)&sq[t][c];
            acc0 = fma2(pack2(k4.x, k4.y), pack2(q4.x, q4.y), acc0);
            acc1 = fma2(pack2(k4.z, k4.w), pack2(q4.z, q4.w), acc1);
        }
        g_P[(size_t)bm * TC * TC + t * TC + j] = hsum2(add2(acc0, acc1));
    }
}

// ---------------------------------------------------------------------------
// P2: serial chunk scan with C in REGISTERS + fp16 snapshots; U computed
// on the fly from k (smem) and a (smem). CTA per (b, 16-row group) = 128
// CTAs x 256 thr. Thread (row=tid&15, cg=tid>>4) owns C[row][16cg..16cg+15].
// Per chunk m: snapshot C -> g_Csh[m]; C = g15*(C + sum_s a[s][row]*k[s]).
// k chunks double-buffered via cp.async (L2-hot: shared by 16 CTAs per b).
// ---------------------------------------------------------------------------
__global__ void __launch_bounds__(256, 1) p2_kernel()
{
    __shared__ float sk[2][TC][LDR];
    __shared__ float sa[2][TC][16];
    __shared__ float sg15[2][16];

    const int b = blockIdx.x >> 4;
    const int rg = blockIdx.x & 15;
    const int rowb = rg * 16;
    const int tid = threadIdx.x;
    const int row = tid & 15;
    const int cg = tid >> 4;
    const size_t mb = (size_t)b * SS * DD;

    const uint32_t sk_u = (uint32_t)__cvta_generic_to_shared(&sk[0][0][0]);
    const uint32_t sa_u = (uint32_t)__cvta_generic_to_shared(&sa[0][0][0]);
    const uint32_t sg_u = (uint32_t)__cvta_generic_to_shared(&sg15[0][0]);

    auto fill = [&](int st, int mm) {
        const int tt = mm * TC;
        const int bm = b * CH + mm;
#pragma unroll
        for (int v = 0; v < 4; v++) {
            int idx = tid + v * 256;
            int t = idx >> 6, gr = idx & 63;
            cp_async16(sk_u + (uint32_t)(((st * TC + t) * LDR + gr * 4) * 4),
                       g_k + mb + (size_t)(tt + t) * DD + gr * 4);
        }
        if (tid < 64) {
            int s = tid >> 2, p = tid & 3;
            cp_async16(sa_u + (uint32_t)(((st * TC + s) * 16 + p * 4) * 4),
                       g_a + (size_t)(bm * TC + s) * DD + rowb + p * 4);
        } else if (tid < 68) {
            int p = tid - 64;
            cp_async16(sg_u + (uint32_t)((st * 16 + p * 4) * 4),
                       g_G + (size_t)(bm * TC + 15) * DD + rowb + p * 4);
        }
    };

    ull Cp[8];
#pragma unroll
    for (int j = 0; j < 8; j++) Cp[j] = 0ull;

    fill(0, 0); cp_commit();
    fill(1, 1); cp_commit();

    for (int m = 0; m < CH; m++) {
        const int st = m & 1;
        cp_wait<1>();
        __syncthreads();

        // snapshot C (fp16) — state at chunk start
        {
            uint4 u0, u1;
            float lo, hi;
            unpack2(Cp[0], lo, hi); u0.x = f2_to_h2(lo, hi);
            unpack2(Cp[1], lo, hi); u0.y = f2_to_h2(lo, hi);
            unpack2(Cp[2], lo, hi); u0.z = f2_to_h2(lo, hi);
            unpack2(Cp[3], lo, hi); u0.w = f2_to_h2(lo, hi);
            unpack2(Cp[4], lo, hi); u1.x = f2_to_h2(lo, hi);
            unpack2(Cp[5], lo, hi); u1.y = f2_to_h2(lo, hi);
            unpack2(Cp[6], lo, hi); u1.z = f2_to_h2(lo, hi);
            unpack2(Cp[7], lo, hi); u1.w = f2_to_h2(lo, hi);
            const int bm = b * CH + m;
            __half* dst = g_Csh + ((size_t)bm * DD + rowb + row) * DD + cg * 16;
            *(uint4*)dst = u0;
            *(uint4*)(dst + 8) = u1;
        }

        // update: C = g15 * (C + sum_s a[s][row] * k[s][cols])
        {
            ull acc[8];
#pragma unroll
            for (int j = 0; j < 8; j++) acc[j] = 0ull;
#pragma unroll 4
            for (int s = 0; s < TC; s++) {
                float as = sa[st][s][row];
                ull as2 = pack2(as, as);
                const float* kp = &sk[st][s][cg * 16];
                float4 k0 = *(const float4*)(kp + 0);
                float4 k1 = *(const float4*)(kp + 4);
                float4 k2 = *(const float4*)(kp + 8);
                float4 k3 = *(const float4*)(kp + 12);
                acc[0] = fma2(as2, pack2(k0.x, k0.y), acc[0]);
                acc[1] = fma2(as2, pack2(k0.z, k0.w), acc[1]);
                acc[2] = fma2(as2, pack2(k1.x, k1.y), acc[2]);
                acc[3] = fma2(as2, pack2(k1.z, k1.w), acc[3]);
                acc[4] = fma2(as2, pack2(k2.x, k2.y), acc[4]);
                acc[5] = fma2(as2, pack2(k2.z, k2.w), acc[5]);
                acc[6] = fma2(as2, pack2(k3.x, k3.y), acc[6]);
                acc[7] = fma2(as2, pack2(k3.z, k3.w), acc[7]);
            }
            float g15v = sg15[st][row];
            ull g2 = pack2(g15v, g15v);
#pragma unroll
            for (int j = 0; j < 8; j++)
                Cp[j] = mul2(g2, add2(Cp[j], acc[j]));
        }
        __syncthreads();

        if (m + 2 < CH) fill(st, m + 2);
        cp_commit();
    }
}

// ---------------------------------------------------------------------------
// P3: per (b,chunk,32-row group) — CQ = Cs.q^T + triangular combine.
// grid = 4096, 128 threads. Thread (r2=tid&15, nh=tid>>4) computes 2x2 tile:
// rows {r2, r2+16} x t {nh, nh+8}.
// ---------------------------------------------------------------------------
struct P3Smem {
    float q[TC][LDR];          // 16.6 KB
    float Cs[32][LDR];         // 33.3 KB (fp32 after conversion)
    float a[TC][32];
    float G[TC][32];
    float P[TC][TC];
    float inv[TC];
    float htile[TC][32];
};

__global__ void __launch_bounds__(128) p3_kernel()
{
    __shared__ P3Smem S;
    const int blk = blockIdx.x;
    const int bm = blk >> 3;
    const int rg = blk & 7;
    const int b = bm >> 6, m = bm & 63;
    const int tid = threadIdx.x;
    const int rowb = rg * 32;
    const size_t mb = (size_t)b * SS * DD;
    const int tt = m * TC;

    // q: 1024 float4 granules
#pragma unroll
    for (int v = 0; v < 8; v++) {
        int idx = tid + v * 128;
        int t = idx >> 6, gr = idx & 63;
        *(float4*)&S.q[t][gr * 4] =
            *(const float4*)(g_q + mb + (size_t)(tt + t) * DD + gr * 4);
    }
    // Cs fp16 -> fp32: 1024 uint4 (8 halfs each)
#pragma unroll
    for (int v = 0; v < 8; v++) {
        int idx = tid + v * 128;
        int r = idx >> 5, u = idx & 31;
        uint4 raw = *(const uint4*)(g_Csh + ((size_t)bm * DD + rowb + r) * DD + u * 8);
        const __half2* hp = (const __half2*)&raw;
        float2 f0 = __half22float2(hp[0]);
        float2 f1 = __half22float2(hp[1]);
        float2 f2 = __half22float2(hp[2]);
        float2 f3 = __half22float2(hp[3]);
        *(float4*)&S.Cs[r][u * 8]     = make_float4(f0.x, f0.y, f1.x, f1.y);
        *(float4*)&S.Cs[r][u * 8 + 4] = make_float4(f2.x, f2.y, f3.x, f3.y);
    }
    // a, G: 16 s x 32 rows = 128 float4 each
#pragma unroll
    for (int v = 0; v < 4; v++) {
        int idx = tid + v * 128;            // 0..511
        int arr = idx >> 7;                 // 0..3: a lo, a hi... use: 0-1 a, 2-3 G
        int rem = idx & 127;
        int s = rem >> 3, p = rem & 7;
        if (arr < 2) {
            int pp = (arr & 1) * 0;         // layout: idx<128 a first half? simpler below
        }
        // simpler: idx<128 -> a part0; 128..255 -> G part0 ... need 128 each
        if (idx < 128)
            *(float4*)&S.a[s][p * 4] =
                *(const float4*)(g_a + (size_t)(bm * TC + s) * DD + rowb + p * 4);
        else if (idx < 256)
            *(float4*)&S.G[s][p * 4] =
                *(const float4*)(g_G + (size_t)(bm * TC + s) * DD + rowb + p * 4);
        else if (idx < 320) {
            int ii = idx - 256;             // 0..63
            int t2 = ii >> 2, p2 = ii & 3;
            *(float4*)&S.P[t2][p2 * 4] =
                *(const float4*)(g_P + (size_t)bm * 256 + t2 * 16 + p2 * 4);
        } else if (idx < 324) {
            int p3 = idx - 320;
            *(float4*)&S.inv[p3 * 4] =
                *(const float4*)(g_inv + b * SS + tt + p3 * 4);
        }
    }
    __syncthreads();

    const int r2 = tid & 15;
    const int nh = tid >> 4;
    const int rA = r2, rB = r2 + 16;
    const int tA = nh, tB = nh + 8;

    ull cAA0 = 0, cAA1 = 0, cAB0 = 0, cAB1 = 0;
    ull cBA0 = 0, cBA1 = 0, cBB0 = 0, cBB1 = 0;
    const float* CrA = &S.Cs[rA][0];
    const float* CrB = &S.Cs[rB][0];
    const float* q0 = &S.q[tA][0];
    const float* q1 = &S.q[tB][0];
#pragma unroll 8
    for (int c = 0; c < DD; c += 4) {
        float4 CA = *(const float4*)(CrA + c);
        float4 CB = *(const float4*)(CrB + c);
        float4 B0 = *(const float4*)(q0 + c);
        float4 B1 = *(const float4*)(q1 + c);
        ull Axy = pack2(CA.x, CA.y), Azw = pack2(CA.z, CA.w);
        ull Bxy = pack2(CB.x, CB.y), Bzw = pack2(CB.z, CB.w);
        ull q0xy = pack2(B0.x, B0.y), q0zw = pack2(B0.z, B0.w);
        ull q1xy = pack2(B1.x, B1.y), q1zw = pack2(B1.z, B1.w);
        cAA0 = fma2(Axy, q0xy, cAA0); cAA1 = fma2(Azw, q0zw, cAA1);
        cAB0 = fma2(Axy, q1xy, cAB0); cAB1 = fma2(Azw, q1zw, cAB1);
        cBA0 = fma2(Bxy, q0xy, cBA0); cBA1 = fma2(Bzw, q0zw, cBA1);
        cBB0 = fma2(Bxy, q1xy, cBB0); cBB1 = fma2(Bzw, q1zw, cBB1);
    }
    float CQ_AA = hsum2(add2(cAA0, cAA1));   // (tA, rA)
    float CQ_AB = hsum2(add2(cAB0, cAB1));   // (tB, rA)
    float CQ_BA = hsum2(add2(cBA0, cBA1));   // (tA, rB)
    float CQ_BB = hsum2(add2(cBB0, cBB1));   // (tB, rB)

    // combine
    {
        float nAA = CQ_AA, nBA = CQ_BA;
#pragma unroll
        for (int s = 0; s < TC; s++)
            if (s <= tA) {
                float p = S.P[tA][s];
                nAA = fmaf(S.a[s][rA], p, nAA);
                nBA = fmaf(S.a[s][rB], p, nBA);
            }
        S.htile[tA][rA] = S.G[tA][rA] * nAA * S.inv[tA];
        S.htile[tA][rB] = S.G[tA][rB] * nBA * S.inv[tA];

        float nAB = CQ_AB, nBB = CQ_BB;
#pragma unroll
        for (int s = 0; s < TC; s++)
            if (s <= tB) {
                float p = S.P[tB][s];
                nAB = fmaf(S.a[s][rA], p, nAB);
                nBB = fmaf(S.a[s][rB], p, nBB);
            }
        S.htile[tB][rA] = S.G[tB][rA] * nAB * S.inv[tB];
        S.htile[tB][rB] = S.G[tB][rB] * nBB * S.inv[tB];
    }
    __syncthreads();

    // coalesced h write: 128 float4 = 16 t x 8 segments
    {
        const int t = tid >> 3, seg = tid & 7;
        *(float4*)(g_h + mb + (size_t)(tt + t) * DD + rowb + seg * 4) =
            *(const float4*)&S.htile[t][seg * 4];
    }
}

// ---------------------------------------------------------------------------
// Launch
// ---------------------------------------------------------------------------
extern "C" void kernel_launch(void* const* d_in, const int* in_sizes, int n_in,
                              void* d_out, int out_size)
{
    const float* x   = (const float*)d_in[0];
    const float* Wq  = (const float*)d_in[1];
    const float* bq  = (const float*)d_in[2];
    const float* Wk  = (const float*)d_in[3];
    const float* bkk = (const float*)d_in[4];
    // d_in[5] = Wv, d_in[6] = bv — unused (reference uses W_q for v)
    const float* Wf  = (const float*)d_in[7];
    const float* bff = (const float*)d_in[8];
    const float* Wi  = (const float*)d_in[9];
    const float* bii = (const float*)d_in[10];
    const float* Wo  = (const float*)d_in[11];
    const float* bo  = (const float*)d_in[12];
    float* out = (float*)d_out;

    float *pq, *pk, *pf, *pi, *ph;
    cudaGetSymbolAddress((void**)&pq, g_q);
    cudaGetSymbolAddress((void**)&pk, g_k);
    cudaGetSymbolAddress((void**)&pf, g_f);
    cudaGetSymbolAddress((void**)&pi, g_i);
    cudaGetSymbolAddress((void**)&ph, g_h);

    gemm4_kernel<<<dim3(2, 64, 4), 256>>>(x, Wq, bq, Wk, bkk, Wf, bff, Wi, bii,
                                          pq, pk, pf, pi);

    nscan_kernel<<<64, 32>>>();
    den_kernel<<<MTOT / 8, 256>>>();

    p1_kernel<<<BB * CH, 256>>>();
    p2_kernel<<<BB * 16, 256>>>();
    p3_kernel<<<BB * CH * 8, 128>>>();

    gemm_out_kernel<<<dim3(2, 64), 256>>>(ph, Wo, bo, out);
}

// round 12
// speedup vs baseline: 1.9847x; 1.0314x over previous
#include <cuda_runtime.h>
#include <cuda_fp16.h>
#include <math.h>
#include <stdint.h>

// Problem dims
constexpr int BB = 8;
constexpr int SS = 1024;
constexpr int DD = 256;
constexpr int MTOT = BB * SS;          // 8192
constexpr int TC = 16;                 // chunk length
constexpr int CH = SS / TC;            // 64 chunks
constexpr int LDR = 260;               // padded smem row stride

// Scratch (device globals — no cudaMalloc allowed)
__device__ float g_q[MTOT * DD];
__device__ float g_k[MTOT * DD];
__device__ float g_f[MTOT * DD];
__device__ float g_i[MTOT * DD];
__device__ float g_n[MTOT * DD];
__device__ float g_h[MTOT * DD];
__device__ float g_inv[MTOT + 64];
// chunkwise scan scratch
__device__ __half g_Csh[(size_t)BB * CH * DD * DD];  // 64 MB: C at chunk start (fp16)
__device__ float g_G[BB * CH * TC * DD];             // gate prefix products
__device__ float g_a[BB * CH * TC * DD];             // normalized input coeffs
__device__ float g_P[BB * CH * TC * TC];             // k_s . q_t per chunk

typedef unsigned long long ull;

// ---- f32x2 helpers ----
__device__ __forceinline__ ull pack2(float lo, float hi) {
    ull r; asm("mov.b64 %0, {%1, %2};" : "=l"(r) : "f"(lo), "f"(hi)); return r;
}
__device__ __forceinline__ ull fma2(ull a, ull b, ull c) {
    ull d; asm("fma.rn.f32x2 %0, %1, %2, %3;" : "=l"(d) : "l"(a), "l"(b), "l"(c)); return d;
}
__device__ __forceinline__ ull mul2(ull a, ull b) {
    ull d; asm("mul.rn.f32x2 %0, %1, %2;" : "=l"(d) : "l"(a), "l"(b)); return d;
}
__device__ __forceinline__ ull add2(ull a, ull b) {
    ull d; asm("add.rn.f32x2 %0, %1, %2;" : "=l"(d) : "l"(a), "l"(b)); return d;
}
__device__ __forceinline__ void unpack2(ull v, float& lo, float& hi) {
    asm("mov.b64 {%0, %1}, %2;" : "=f"(lo), "=f"(hi) : "l"(v));
}
__device__ __forceinline__ float hsum2(ull v) {
    float lo, hi; unpack2(v, lo, hi); return lo + hi;
}
__device__ __forceinline__ uint32_t f2_to_h2(float lo, float hi) {
    __half2 h = __floats2half2_rn(lo, hi);
    return *(uint32_t*)&h;
}

// ---- cp.async helpers ----
__device__ __forceinline__ void cp_async16(uint32_t saddr, const void* gptr) {
    asm volatile("cp.async.ca.shared.global [%0], [%1], 16;" :: "r"(saddr), "l"(gptr));
}
__device__ __forceinline__ void cp_commit() { asm volatile("cp.async.commit_group;"); }
template <int N>
__device__ __forceinline__ void cp_wait() {
    asm volatile("cp.async.wait_group %0;" :: "n"(N));
}

// ---------------------------------------------------------------------------
// Fused input GEMM: z selects (Wq,Wk,Wf,Wi); grid (2,64,4), 2 CTAs/SM.
// ---------------------------------------------------------------------------
__global__ void __launch_bounds__(256, 2) gemm4_kernel(
    const float* __restrict__ x,
    const float* __restrict__ W0, const float* __restrict__ b0,
    const float* __restrict__ W1, const float* __restrict__ b1,
    const float* __restrict__ W2, const float* __restrict__ b2,
    const float* __restrict__ W3, const float* __restrict__ b3,
    float* __restrict__ o0, float* __restrict__ o1,
    float* __restrict__ o2, float* __restrict__ o3)
{
    __shared__ float As[8][132];
    __shared__ float Bs[8][132];

    const int z = blockIdx.z;
    const float* W = (z == 0) ? W0 : (z == 1) ? W1 : (z == 2) ? W2 : W3;
    const float* bias = (z == 0) ? b0 : (z == 1) ? b1 : (z == 2) ? b2 : b3;
    float* out = (z == 0) ? o0 : (z == 1) ? o1 : (z == 2) ? o2 : o3;

    const int tid = threadIdx.x;
    const int m0 = blockIdx.y * 128;
    const int n0 = blockIdx.x * 128;
    const int lm = tid >> 1;
    const int lk = (tid & 1) << 2;
    const int tx = tid & 15;
    const int ty = tid >> 4;

    ull acc2[8][4] = {};

    float4 a4 = *(const float4*)(x + (size_t)(m0 + lm) * DD + lk);
    float4 w4 = *(const float4*)(W + (size_t)(n0 + lm) * DD + lk);

    for (int k0 = 0; k0 < DD; k0 += 8) {
        __syncthreads();
        As[lk + 0][lm] = a4.x; As[lk + 1][lm] = a4.y;
        As[lk + 2][lm] = a4.z; As[lk + 3][lm] = a4.w;
        Bs[lk + 0][lm] = w4.x; Bs[lk + 1][lm] = w4.y;
        Bs[lk + 2][lm] = w4.z; Bs[lk + 3][lm] = w4.w;
        __syncthreads();
        if (k0 + 8 < DD) {
            a4 = *(const float4*)(x + (size_t)(m0 + lm) * DD + k0 + 8 + lk);
            w4 = *(const float4*)(W + (size_t)(n0 + lm) * DD + k0 + 8 + lk);
        }
#pragma unroll
        for (int kk = 0; kk < 8; kk++) {
            float4 av0 = *(const float4*)&As[kk][ty * 8];
            float4 av1 = *(const float4*)&As[kk][ty * 8 + 4];
            float4 bv0 = *(const float4*)&Bs[kk][tx * 8];
            float4 bv1 = *(const float4*)&Bs[kk][tx * 8 + 4];
            ull b0p = pack2(bv0.x, bv0.y);
            ull b1p = pack2(bv0.z, bv0.w);
            ull b2p = pack2(bv1.x, bv1.y);
            ull b3p = pack2(bv1.z, bv1.w);
            float am[8] = {av0.x, av0.y, av0.z, av0.w, av1.x, av1.y, av1.z, av1.w};
#pragma unroll
            for (int i2 = 0; i2 < 8; i2++) {
                ull aa = pack2(am[i2], am[i2]);
                acc2[i2][0] = fma2(aa, b0p, acc2[i2][0]);
                acc2[i2][1] = fma2(aa, b1p, acc2[i2][1]);
                acc2[i2][2] = fma2(aa, b2p, acc2[i2][2]);
                acc2[i2][3] = fma2(aa, b3p, acc2[i2][3]);
            }
        }
    }

    float4 bb0 = *(const float4*)(bias + n0 + tx * 8);
    float4 bb1 = *(const float4*)(bias + n0 + tx * 8 + 4);
    float bb[8] = {bb0.x, bb0.y, bb0.z, bb0.w, bb1.x, bb1.y, bb1.z, bb1.w};
#pragma unroll
    for (int i2 = 0; i2 < 8; i2++) {
        float r[8];
        unpack2(acc2[i2][0], r[0], r[1]);
        unpack2(acc2[i2][1], r[2], r[3]);
        unpack2(acc2[i2][2], r[4], r[5]);
        unpack2(acc2[i2][3], r[6], r[7]);
        float4 q0, q1;
#pragma unroll
        for (int j2 = 0; j2 < 8; j2++) {
            float v = r[j2] + bb[j2];
            if (z == 2) v = 1.0f / (1.0f + expf(-v));
            else if (z == 3) v = expf(v);
            if (j2 < 4) (&q0.x)[j2] = v; else (&q1.x)[j2 - 4] = v;
        }
        float* dst = out + (size_t)(m0 + ty * 8 + i2) * DD + n0 + tx * 8;
        *(float4*)dst = q0;
        *(float4*)(dst + 4) = q1;
    }
}

// ---------------------------------------------------------------------------
// Output GEMM (2 CTAs/SM)
// ---------------------------------------------------------------------------
__global__ void __launch_bounds__(256, 2) gemm_out_kernel(
    const float* __restrict__ A, const float* __restrict__ W,
    const float* __restrict__ bias, float* __restrict__ out)
{
    __shared__ float As[8][132];
    __shared__ float Bs[8][132];

    const int tid = threadIdx.x;
    const int m0 = blockIdx.y * 128;
    const int n0 = blockIdx.x * 128;
    const int lm = tid >> 1;
    const int lk = (tid & 1) << 2;
    const int tx = tid & 15;
    const int ty = tid >> 4;

    ull acc2[8][4] = {};

    float4 a4 = *(const float4*)(A + (size_t)(m0 + lm) * DD + lk);
    float4 w4 = *(const float4*)(W + (size_t)(n0 + lm) * DD + lk);

    for (int k0 = 0; k0 < DD; k0 += 8) {
        __syncthreads();
        As[lk + 0][lm] = a4.x; As[lk + 1][lm] = a4.y;
        As[lk + 2][lm] = a4.z; As[lk + 3][lm] = a4.w;
        Bs[lk + 0][lm] = w4.x; Bs[lk + 1][lm] = w4.y;
        Bs[lk + 2][lm] = w4.z; Bs[lk + 3][lm] = w4.w;
        __syncthreads();
        if (k0 + 8 < DD) {
            a4 = *(const float4*)(A + (size_t)(m0 + lm) * DD + k0 + 8 + lk);
            w4 = *(const float4*)(W + (size_t)(n0 + lm) * DD + k0 + 8 + lk);
        }
#pragma unroll
        for (int kk = 0; kk < 8; kk++) {
            float4 av0 = *(const float4*)&As[kk][ty * 8];
            float4 av1 = *(const float4*)&As[kk][ty * 8 + 4];
            float4 bv0 = *(const float4*)&Bs[kk][tx * 8];
            float4 bv1 = *(const float4*)&Bs[kk][tx * 8 + 4];
            ull b0p = pack2(bv0.x, bv0.y);
            ull b1p = pack2(bv0.z, bv0.w);
            ull b2p = pack2(bv1.x, bv1.y);
            ull b3p = pack2(bv1.z, bv1.w);
            float am[8] = {av0.x, av0.y, av0.z, av0.w, av1.x, av1.y, av1.z, av1.w};
#pragma unroll
            for (int i2 = 0; i2 < 8; i2++) {
                ull aa = pack2(am[i2], am[i2]);
                acc2[i2][0] = fma2(aa, b0p, acc2[i2][0]);
                acc2[i2][1] = fma2(aa, b1p, acc2[i2][1]);
                acc2[i2][2] = fma2(aa, b2p, acc2[i2][2]);
                acc2[i2][3] = fma2(aa, b3p, acc2[i2][3]);
            }
        }
    }

    float4 bb0 = *(const float4*)(bias + n0 + tx * 8);
    float4 bb1 = *(const float4*)(bias + n0 + tx * 8 + 4);
    float bb[8] = {bb0.x, bb0.y, bb0.z, bb0.w, bb1.x, bb1.y, bb1.z, bb1.w};
#pragma unroll
    for (int i2 = 0; i2 < 8; i2++) {
        float r[8];
        unpack2(acc2[i2][0], r[0], r[1]);
        unpack2(acc2[i2][1], r[2], r[3]);
        unpack2(acc2[i2][2], r[4], r[5]);
        unpack2(acc2[i2][3], r[6], r[7]);
        float4 q0, q1;
#pragma unroll
        for (int j2 = 0; j2 < 8; j2++) {
            float v = r[j2] + bb[j2];
            if (j2 < 4) (&q0.x)[j2] = v; else (&q1.x)[j2 - 4] = v;
        }
        float* dst = out + (size_t)(m0 + ty * 8 + i2) * DD + n0 + tx * 8;
        *(float4*)dst = q0;
        *(float4*)(dst + 4) = q1;
    }
}

// ---------------------------------------------------------------------------
// n-scan: 2048 chains, deep unroll for MLP
// ---------------------------------------------------------------------------
__global__ void nscan_kernel()
{
    const int cid = blockIdx.x * 32 + threadIdx.x;
    const int b = cid >> 8;
    const int j = cid & 255;
    const size_t base = (size_t)b * SS * DD + j;
    float n = 0.0f;
#pragma unroll 16
    for (int t = 0; t < SS; t++) {
        size_t o = base + (size_t)t * DD;
        n = fmaf(g_f[o], n, g_i[o] * g_k[o]);
        g_n[o] = n;
    }
}

// ---------------------------------------------------------------------------
// P1: per (b,chunk) — gates G/a, P = k.q^T, AND inv_den (n staged in smem).
// grid = 512, 256 threads. Must run AFTER nscan.
// ---------------------------------------------------------------------------
__global__ void __launch_bounds__(256) p1_kernel()
{
    __shared__ float sk[TC][LDR];
    __shared__ float sq[TC][DD];
    __shared__ float sn[TC][DD];

    const int bm = blockIdx.x;
    const int b = bm >> 6, m = bm & 63;
    const int tid = threadIdx.x;
    const size_t mb = (size_t)b * SS * DD;
    const int tt = m * TC;

#pragma unroll
    for (int v = 0; v < 4; v++) {
        int idx = tid + v * 256;
        int t = idx >> 6, gr = idx & 63;
        *(float4*)&sk[t][gr * 4] =
            *(const float4*)(g_k + mb + (size_t)(tt + t) * DD + gr * 4);
        *(float4*)&sq[t][gr * 4] =
            *(const float4*)(g_q + mb + (size_t)(tt + t) * DD + gr * 4);
        *(float4*)&sn[t][gr * 4] =
            *(const float4*)(g_n + mb + (size_t)(tt + t) * DD + gr * 4);
    }
    // gates: thread = channel i
    {
        const int i = tid;
        float g = 1.0f;
#pragma unroll
        for (int u = 0; u < TC; u++) {
            size_t o = mb + (size_t)(tt + u) * DD + i;
            float f = g_f[o], ii = g_i[o], vv = g_q[o];   // v == q
            g *= f;
            float av = __fdividef(ii * vv, g);
            g_G[(size_t)(bm * TC + u) * DD + i] = g;
            g_a[(size_t)(bm * TC + u) * DD + i] = av;
        }
    }
    __syncthreads();

    // P[t][j] = k_j . q_t
    {
        const int t = tid >> 4, j = tid & 15;
        ull acc0 = 0, acc1 = 0;
#pragma unroll 8
        for (int c = 0; c < DD; c += 4) {
            float4 k4 = *(const float4*)&sk[j][c];
            float4 q4 = *(const float4*)&sq[t][c];
            acc0 = fma2(pack2(k4.x, k4.y), pack2(q4.x, q4.y), acc0);
            acc1 = fma2(pack2(k4.z, k4.w), pack2(q4.z, q4.w), acc1);
        }
        g_P[(size_t)bm * TC * TC + t * TC + j] = hsum2(add2(acc0, acc1));
    }
    // inv_den: 16 threads, one per t (runs alongside tail of dots)
    if (tid < TC) {
        const int t = tid;
        ull a0 = 0, a1 = 0;
#pragma unroll 8
        for (int c = 0; c < DD; c += 4) {
            float4 n4 = *(const float4*)&sn[t][c];
            float4 q4 = *(const float4*)&sq[t][c];
            a0 = fma2(pack2(n4.x, n4.y), pack2(q4.x, q4.y), a0);
            a1 = fma2(pack2(n4.z, n4.w), pack2(q4.z, q4.w), a1);
        }
        float d = hsum2(add2(a0, a1));
        g_inv[b * SS + tt + t] = 1.0f / fmaxf(fabsf(d), 1.0f);
    }
}

// ---------------------------------------------------------------------------
// P2: serial chunk scan, C in registers, fp16 snapshots. 4 rows x 4 cols
// per thread (halves LDS vs 1x16). CTA per (b, 16-row group) = 128 CTAs.
// Thread (rq=tid>>6 -> rows 4rq.., cq=tid&63 -> cols 4cq..).
// ---------------------------------------------------------------------------
__global__ void __launch_bounds__(256, 1) p2_kernel()
{
    __shared__ float sk[2][TC][LDR];
    __shared__ float sa[2][TC][16];
    __shared__ float sg15[2][16];

    const int b = blockIdx.x >> 4;
    const int rg = blockIdx.x & 15;
    const int rowb = rg * 16;
    const int tid = threadIdx.x;
    const int rq = tid >> 6;            // row group: rows 4rq..4rq+3
    const int cq = tid & 63;            // col group: cols 4cq..4cq+3
    const size_t mb = (size_t)b * SS * DD;

    const uint32_t sk_u = (uint32_t)__cvta_generic_to_shared(&sk[0][0][0]);
    const uint32_t sa_u = (uint32_t)__cvta_generic_to_shared(&sa[0][0][0]);
    const uint32_t sg_u = (uint32_t)__cvta_generic_to_shared(&sg15[0][0]);

    auto fill = [&](int st, int mm) {
        const int tt = mm * TC;
        const int bm = b * CH + mm;
#pragma unroll
        for (int v = 0; v < 4; v++) {
            int idx = tid + v * 256;
            int t = idx >> 6, gr = idx & 63;
            cp_async16(sk_u + (uint32_t)(((st * TC + t) * LDR + gr * 4) * 4),
                       g_k + mb + (size_t)(tt + t) * DD + gr * 4);
        }
        if (tid < 64) {
            int s = tid >> 2, p = tid & 3;
            cp_async16(sa_u + (uint32_t)(((st * TC + s) * 16 + p * 4) * 4),
                       g_a + (size_t)(bm * TC + s) * DD + rowb + p * 4);
        } else if (tid < 68) {
            int p = tid - 64;
            cp_async16(sg_u + (uint32_t)((st * 16 + p * 4) * 4),
                       g_G + (size_t)(bm * TC + 15) * DD + rowb + p * 4);
        }
    };

    ull Cp[4][2];                       // 4 rows x 4 cols
#pragma unroll
    for (int r = 0; r < 4; r++) { Cp[r][0] = 0ull; Cp[r][1] = 0ull; }

    fill(0, 0); cp_commit();
    fill(1, 1); cp_commit();

    for (int m = 0; m < CH; m++) {
        const int st = m & 1;
        cp_wait<1>();
        __syncthreads();

        // snapshot C (fp16): per row, 4 halfs = 8 B (coalesced across cq)
        {
            const int bm = b * CH + m;
#pragma unroll
            for (int r = 0; r < 4; r++) {
                float l0, h0, l1, h1;
                unpack2(Cp[r][0], l0, h0);
                unpack2(Cp[r][1], l1, h1);
                uint2 u;
                u.x = f2_to_h2(l0, h0);
                u.y = f2_to_h2(l1, h1);
                __half* dst = g_Csh + ((size_t)bm * DD + rowb + rq * 4 + r) * DD + cq * 4;
                *(uint2*)dst = u;
            }
        }

        // update: C = g15 * (C + sum_s a[s][rows] * k[s][cols])
        {
            ull acc[4][2];
#pragma unroll
            for (int r = 0; r < 4; r++) { acc[r][0] = 0ull; acc[r][1] = 0ull; }
#pragma unroll 4
            for (int s = 0; s < TC; s++) {
                float4 a4 = *(const float4*)&sa[st][s][rq * 4];
                float4 k4 = *(const float4*)&sk[st][s][cq * 4];
                ull kxy = pack2(k4.x, k4.y), kzw = pack2(k4.z, k4.w);
                ull a0 = pack2(a4.x, a4.x);
                ull a1 = pack2(a4.y, a4.y);
                ull a2 = pack2(a4.z, a4.z);
                ull a3 = pack2(a4.w, a4.w);
                acc[0][0] = fma2(a0, kxy, acc[0][0]); acc[0][1] = fma2(a0, kzw, acc[0][1]);
                acc[1][0] = fma2(a1, kxy, acc[1][0]); acc[1][1] = fma2(a1, kzw, acc[1][1]);
                acc[2][0] = fma2(a2, kxy, acc[2][0]); acc[2][1] = fma2(a2, kzw, acc[2][1]);
                acc[3][0] = fma2(a3, kxy, acc[3][0]); acc[3][1] = fma2(a3, kzw, acc[3][1]);
            }
            float4 g4 = *(const float4*)&sg15[st][rq * 4];
            float gv[4] = {g4.x, g4.y, g4.z, g4.w};
#pragma unroll
            for (int r = 0; r < 4; r++) {
                ull g2 = pack2(gv[r], gv[r]);
                Cp[r][0] = mul2(g2, add2(Cp[r][0], acc[r][0]));
                Cp[r][1] = mul2(g2, add2(Cp[r][1], acc[r][1]));
            }
        }
        __syncthreads();

        if (m + 2 < CH) fill(st, m + 2);
        cp_commit();
    }
}

// ---------------------------------------------------------------------------
// P3: per (b,chunk,32-row group) — CQ = Cs.q^T + triangular combine.
// grid = 4096, 128 threads.
// ---------------------------------------------------------------------------
struct P3Smem {
    float q[TC][LDR];
    float Cs[32][LDR];
    float a[TC][32];
    float G[TC][32];
    float P[TC][TC];
    float inv[TC];
    float htile[TC][32];
};

__global__ void __launch_bounds__(128) p3_kernel()
{
    __shared__ P3Smem S;
    const int blk = blockIdx.x;
    const int bm = blk >> 3;
    const int rg = blk & 7;
    const int b = bm >> 6, m = bm & 63;
    const int tid = threadIdx.x;
    const int rowb = rg * 32;
    const size_t mb = (size_t)b * SS * DD;
    const int tt = m * TC;

#pragma unroll
    for (int v = 0; v < 8; v++) {
        int idx = tid + v * 128;
        int t = idx >> 6, gr = idx & 63;
        *(float4*)&S.q[t][gr * 4] =
            *(const float4*)(g_q + mb + (size_t)(tt + t) * DD + gr * 4);
    }
#pragma unroll
    for (int v = 0; v < 8; v++) {
        int idx = tid + v * 128;
        int r = idx >> 5, u = idx & 31;
        uint4 raw = *(const uint4*)(g_Csh + ((size_t)bm * DD + rowb + r) * DD + u * 8);
        const __half2* hp = (const __half2*)&raw;
        float2 f0 = __half22float2(hp[0]);
        float2 f1 = __half22float2(hp[1]);
        float2 f2 = __half22float2(hp[2]);
        float2 f3 = __half22float2(hp[3]);
        *(float4*)&S.Cs[r][u * 8]     = make_float4(f0.x, f0.y, f1.x, f1.y);
        *(float4*)&S.Cs[r][u * 8 + 4] = make_float4(f2.x, f2.y, f3.x, f3.y);
    }
#pragma unroll
    for (int v = 0; v < 4; v++) {
        int idx = tid + v * 128;
        int s = (idx & 127) >> 3, p = idx & 7;
        if (idx < 128)
            *(float4*)&S.a[s][p * 4] =
                *(const float4*)(g_a + (size_t)(bm * TC + s) * DD + rowb + p * 4);
        else if (idx < 256)
            *(float4*)&S.G[s][p * 4] =
                *(const float4*)(g_G + (size_t)(bm * TC + s) * DD + rowb + p * 4);
        else if (idx < 320) {
            int ii = idx - 256;
            int t2 = ii >> 2, p2 = ii & 3;
            *(float4*)&S.P[t2][p2 * 4] =
                *(const float4*)(g_P + (size_t)bm * 256 + t2 * 16 + p2 * 4);
        } else if (idx < 324) {
            int p3 = idx - 320;
            *(float4*)&S.inv[p3 * 4] =
                *(const float4*)(g_inv + b * SS + tt + p3 * 4);
        }
    }
    __syncthreads();

    const int r2 = tid & 15;
    const int nh = tid >> 4;
    const int rA = r2, rB = r2 + 16;
    const int tA = nh, tB = nh + 8;

    ull cAA0 = 0, cAA1 = 0, cAB0 = 0, cAB1 = 0;
    ull cBA0 = 0, cBA1 = 0, cBB0 = 0, cBB1 = 0;
    const float* CrA = &S.Cs[rA][0];
    const float* CrB = &S.Cs[rB][0];
    const float* q0 = &S.q[tA][0];
    const float* q1 = &S.q[tB][0];
#pragma unroll 8
    for (int c = 0; c < DD; c += 4) {
        float4 CA = *(const float4*)(CrA + c);
        float4 CB = *(const float4*)(CrB + c);
        float4 B0 = *(const float4*)(q0 + c);
        float4 B1 = *(const float4*)(q1 + c);
        ull Axy = pack2(CA.x, CA.y), Azw = pack2(CA.z, CA.w);
        ull Bxy = pack2(CB.x, CB.y), Bzw = pack2(CB.z, CB.w);
        ull q0xy = pack2(B0.x, B0.y), q0zw = pack2(B0.z, B0.w);
        ull q1xy = pack2(B1.x, B1.y), q1zw = pack2(B1.z, B1.w);
        cAA0 = fma2(Axy, q0xy, cAA0); cAA1 = fma2(Azw, q0zw, cAA1);
        cAB0 = fma2(Axy, q1xy, cAB0); cAB1 = fma2(Azw, q1zw, cAB1);
        cBA0 = fma2(Bxy, q0xy, cBA0); cBA1 = fma2(Bzw, q0zw, cBA1);
        cBB0 = fma2(Bxy, q1xy, cBB0); cBB1 = fma2(Bzw, q1zw, cBB1);
    }
    float CQ_AA = hsum2(add2(cAA0, cAA1));
    float CQ_AB = hsum2(add2(cAB0, cAB1));
    float CQ_BA = hsum2(add2(cBA0, cBA1));
    float CQ_BB = hsum2(add2(cBB0, cBB1));

    {
        float nAA = CQ_AA, nBA = CQ_BA;
#pragma unroll
        for (int s = 0; s < TC; s++)
            if (s <= tA) {
                float p = S.P[tA][s];
                nAA = fmaf(S.a[s][rA], p, nAA);
                nBA = fmaf(S.a[s][rB], p, nBA);
            }
        S.htile[tA][rA] = S.G[tA][rA] * nAA * S.inv[tA];
        S.htile[tA][rB] = S.G[tA][rB] * nBA * S.inv[tA];

        float nAB = CQ_AB, nBB = CQ_BB;
#pragma unroll
        for (int s = 0; s < TC; s++)
            if (s <= tB) {
                float p = S.P[tB][s];
                nAB = fmaf(S.a[s][rA], p, nAB);
                nBB = fmaf(S.a[s][rB], p, nBB);
            }
        S.htile[tB][rA] = S.G[tB][rA] * nAB * S.inv[tB];
        S.htile[tB][rB] = S.G[tB][rB] * nBB * S.inv[tB];
    }
    __syncthreads();

    {
        const int t = tid >> 3, seg = tid & 7;
        *(float4*)(g_h + mb + (size_t)(tt + t) * DD + rowb + seg * 4) =
            *(const float4*)&S.htile[t][seg * 4];
    }
}

// ---------------------------------------------------------------------------
// Launch
// ---------------------------------------------------------------------------
extern "C" void kernel_launch(void* const* d_in, const int* in_sizes, int n_in,
                              void* d_out, int out_size)
{
    const float* x   = (const float*)d_in[0];
    const float* Wq  = (const float*)d_in[1];
    const float* bq  = (const float*)d_in[2];
    const float* Wk  = (const float*)d_in[3];
    const float* bkk = (const float*)d_in[4];
    // d_in[5] = Wv, d_in[6] = bv — unused (reference uses W_q for v)
    const float* Wf  = (const float*)d_in[7];
    const float* bff = (const float*)d_in[8];
    const float* Wi  = (const float*)d_in[9];
    const float* bii = (const float*)d_in[10];
    const float* Wo  = (const float*)d_in[11];
    const float* bo  = (const float*)d_in[12];
    float* out = (float*)d_out;

    float *pq, *pk, *pf, *pi, *ph;
    cudaGetSymbolAddress((void**)&pq, g_q);
    cudaGetSymbolAddress((void**)&pk, g_k);
    cudaGetSymbolAddress((void**)&pf, g_f);
    cudaGetSymbolAddress((void**)&pi, g_i);
    cudaGetSymbolAddress((void**)&ph, g_h);

    gemm4_kernel<<<dim3(2, 64, 4), 256>>>(x, Wq, bq, Wk, bkk, Wf, bff, Wi, bii,
                                          pq, pk, pf, pi);

    nscan_kernel<<<64, 32>>>();
    p1_kernel<<<BB * CH, 256>>>();      // also computes inv_den (needs nscan)
    p2_kernel<<<BB * 16, 256>>>();
    p3_kernel<<<BB * CH * 8, 128>>>();

    gemm_out_kernel<<<dim3(2, 64), 256>>>(ph, Wo, bo, out);
}